// round 10
// baseline (speedup 1.0000x reference)
#include <cuda_runtime.h>

#define NQ 12
#define DIM 4096
#define ST 512     // setup threads
#define CT 256     // contract threads

typedef unsigned long long ull;

// Row vectors v_j[n] = <j|U|n>, packed lanes (j=0, j=1): (re, im) per n.
__device__ ulonglong2 g_v2[DIM];
// Split-K partials: [quarter][group32][lane] -> (re, im) packed.
__device__ ulonglong2 g_part4[4][256][32];

// ---- packed f32x2 helpers ----
__device__ __forceinline__ ull pack2(float lo, float hi) {
    ull r; asm("mov.b64 %0, {%1, %2};" : "=l"(r) : "f"(lo), "f"(hi)); return r;
}
__device__ __forceinline__ ull bcast2(float v) { return pack2(v, v); }
__device__ __forceinline__ void unpack2(ull v, float& lo, float& hi) {
    asm("mov.b64 {%0, %1}, %2;" : "=f"(lo), "=f"(hi) : "l"(v));
}
__device__ __forceinline__ ull fma2(ull a, ull b, ull c) {
    ull d; asm("fma.rn.f32x2 %0, %1, %2, %3;" : "=l"(d) : "l"(a), "l"(b), "l"(c)); return d;
}
__device__ __forceinline__ ull mul2(ull a, ull b) {
    ull d; asm("mul.rn.f32x2 %0, %1, %2;" : "=l"(d) : "l"(a), "l"(b)); return d;
}
__device__ __forceinline__ ull add2(ull a, ull b) {
    ull d; asm("add.rn.f32x2 %0, %1, %2;" : "=l"(d) : "l"(a), "l"(b)); return d;
}

// Shared-memory mapping with 65-row pitch: bank-conflict-free for all passes.
__device__ __forceinline__ int pnm(int n) { return 65 * (n >> 6) + (n & 63); }

// 12-bit inverse Gray code (prefix XOR).
__device__ __forceinline__ int grayinv(int i) {
    i ^= i >> 1; i ^= i >> 2; i ^= i >> 4; i ^= i >> 8;
    return i;
}

__device__ __forceinline__ float2 cmulc(float2 a, float2 b) {
    return make_float2(a.x * b.x - a.y * b.y, a.x * b.y + a.y * b.x);
}
__device__ __forceinline__ float2 selE(float2 e, int bit) {   // bit ? e : conj(e)
    return make_float2(e.x, bit ? e.y : -e.y);
}
__device__ __forceinline__ void crot(ull& r, ull& i, float2 f) {
    ull fx = bcast2(f.x), fy = bcast2(f.y), nfy = bcast2(-f.y);
    ull nr = fma2(fx, r, mul2(nfy, i));
    ull ni = fma2(fx, i, mul2(fy, r));
    r = nr; i = ni;
}

// Per-pass index assignment (T = tid 0..511, k = 0..7 owns the pass's 3 bits).
__device__ __forceinline__ int idx_p(int p, int T, int k) {
    int t6 = T & 63, th = T >> 6;
    if (p == 0) return (t6 << 6) | (th << 3) | k;     // k = bits 0-2
    if (p == 1) return (t6 << 6) | (k << 3) | th;     // k = bits 3-5
    if (p == 2) return (th << 9) | (k << 6) | t6;     // k = bits 6-8
    return (k << 9) | (th << 6) | t6;                 // k = bits 9-11
}

// Row x RY gates: 3 gates, gate m on k-bit m (wire = 11 - basebit - m).
__device__ __forceinline__ void apply3(const float* C, const float* S,
                                       int basebit, ull* vr, ull* vi)
{
#pragma unroll
    for (int m = 0; m < 3; ++m) {
        int wire = 11 - basebit - m;
        float c = C[wire], s = S[wire];
        ull c2 = bcast2(c), s2 = bcast2(s), ns2 = bcast2(-s);
#pragma unroll
        for (int k = 0; k < 8; ++k) {
            if (k & (1 << m)) continue;
            int k1 = k | (1 << m);
            ull ar = vr[k], ai = vi[k], br = vr[k1], bi = vi[k1];
            vr[k]  = fma2(c2, ar, mul2(s2, br));
            vi[k]  = fma2(c2, ai, mul2(s2, bi));
            vr[k1] = fma2(c2, br, mul2(ns2, ar));
            vi[k1] = fma2(c2, bi, mul2(ns2, ai));
        }
    }
}

__device__ __forceinline__ void ldp(const ull* sre, const ull* sim, int p, int T,
                                    ull* vr, ull* vi) {
#pragma unroll
    for (int k = 0; k < 8; ++k) {
        int pn = pnm(idx_p(p, T, k));
        vr[k] = sre[pn]; vi[k] = sim[pn];
    }
}
__device__ __forceinline__ void ldp0_gray(const ull* sre, const ull* sim, int T,
                                          ull* vr, ull* vi) {
#pragma unroll
    for (int k = 0; k < 8; ++k) {
        int pn = pnm(grayinv(idx_p(0, T, k)));
        vr[k] = sre[pn]; vi[k] = sim[pn];
    }
}
__device__ __forceinline__ void stp(ull* sre, ull* sim, int p, int T,
                                    const ull* vr, const ull* vi) {
#pragma unroll
    for (int k = 0; k < 8; ++k) {
        int pn = pnm(idx_p(p, T, k));
        sre[pn] = vr[k]; sim[pn] = vi[k];
    }
}

// Diagonal (pass-0 layout). idx bits [11..6]=T&63, [5..3]=T>>6, [2..0]=k.
__device__ __forceinline__ void diag_p0(const float2* E, int T, ull* vr, ull* vi) {
    float2 tp = selE(E[0], (T >> 5) & 1);
#pragma unroll
    for (int w = 1; w < 6; ++w) tp = cmulc(tp, selE(E[w], (T >> (5 - w)) & 1));
#pragma unroll
    for (int w = 6; w < 9; ++w) tp = cmulc(tp, selE(E[w], (T >> (14 - w)) & 1));
#pragma unroll
    for (int k = 0; k < 8; ++k) {
        float2 kt = cmulc(selE(E[9], (k >> 2) & 1),
                          cmulc(selE(E[10], (k >> 1) & 1), selE(E[11], k & 1)));
        crot(vr[k], vi[k], cmulc(tp, kt));
    }
}

// Diagonal (pass-3 layout). idx bits [11..9]=k, [8..0]=T.
__device__ __forceinline__ void diag_p3(const float2* E, int T, ull* vr, ull* vi) {
    float2 tp = selE(E[3], (T >> 8) & 1);
#pragma unroll
    for (int w = 4; w < 12; ++w) tp = cmulc(tp, selE(E[w], (T >> (11 - w)) & 1));
#pragma unroll
    for (int k = 0; k < 8; ++k) {
        float2 kt = cmulc(selE(E[0], (k >> 2) & 1),
                          cmulc(selE(E[1], (k >> 1) & 1), selE(E[2], k & 1)));
        crot(vr[k], vi[k], cmulc(tp, kt));
    }
}

// ====================== SETUP: v = rows <j|U (512 threads, radix-8) =========
__global__ __launch_bounds__(ST)
void setup_kernel(const float* __restrict__ params)
{
    extern __shared__ ull smem[];
    ull* sre = smem;           // 64 rows x 65 pitch = 4160 ull
    ull* sim = smem + 4160;
    __shared__ float  sC[3][12], sS[3][12];
    __shared__ float2 sEA[3][12], sEB[3][12];   // e^{+i alpha/2}, e^{+i beta/2}

    const int T = threadIdx.x;

    if (T < 36) {
        int layer = T / 12, q = T % 12;
        const float* p = params + T * 3;
        float sa, ca; sincosf(0.5f * p[0], &sa, &ca);
        float sb, cb; sincosf(0.5f * p[1], &sb, &cb);
        float sc, cc; sincosf(0.5f * p[2], &sc, &cc);
        float2 m00 = make_float2( cb * ca, -sb * sa);
        float2 m10 = make_float2( cb * sa, -sb * ca);
        float2 e0 = make_float2(cc, -sc);
        float2 e1 = make_float2(cc,  sc);
        float2 u00 = cmulc(e0, m00);
        float2 u10 = cmulc(e1, m10);
        float ct = sqrtf(u00.x * u00.x + u00.y * u00.y);
        float st = sqrtf(u10.x * u10.x + u10.y * u10.y);
        float ApB = -2.0f * atan2f(u00.y, u00.x);
        float AmB =  2.0f * atan2f(u10.y, u10.x);
        float alpha = 0.5f * (ApB + AmB);
        float beta  = 0.5f * (ApB - AmB);
        sC[layer][q] = ct; sS[layer][q] = st;
        float s2, c2;
        sincosf(0.5f * alpha, &s2, &c2); sEA[layer][q] = make_float2(c2, s2);
        sincosf(0.5f * beta,  &s2, &c2); sEB[layer][q] = make_float2(c2, s2);
    }
    __syncthreads();

    ull vr[8], vi[8];

    // ---- Analytic layer-2 row at m = grayinv(idx), pass-0 ownership.
    {
        int t6 = T & 63, th = T >> 6;
        int thi = (t6 << 3) | th;               // idx bits 11..3
        int pt = __popc(thi) & 1;
        int mh = thi ^ (thi >> 1); mh ^= mh >> 2; mh ^= mh >> 4; mh ^= mh >> 8;
        float realH = 1.0f;
        float2 cH = make_float2(1.0f, 0.0f);
#pragma unroll
        for (int w = 0; w < 9; ++w) {           // wires 0..8 <- mh bits 8..0
            int bit = (mh >> (8 - w)) & 1;
            realH *= bit ? -sS[2][w] : sC[2][w];
            cH = cmulc(cH, selE(sEB[2][w], bit));
        }
        float realT[8]; ull rA[8]; float2 cT[8];
#pragma unroll
        for (int m = 0; m < 8; ++m) {
            int b2 = (m >> 2) & 1, b1 = (m >> 1) & 1, b0 = m & 1;
            realT[m] = (b2 ? -sS[2][9] : sC[2][9]) * (b1 ? -sS[2][10] : sC[2][10]);
            rA[m] = pack2(b0 ? -sS[2][11] : sC[2][11],
                          b0 ?  sC[2][11] : sS[2][11]);
            cT[m] = cmulc(selE(sEB[2][9], b2),
                          cmulc(selE(sEB[2][10], b1), selE(sEB[2][11], b0)));
        }
#pragma unroll
        for (int k = 0; k < 8; ++k) {
            int g = (k ^ (k >> 1) ^ (k >> 2)) & 7;
            float rt = pt ? realT[g ^ 7] : realT[g];
            ull   ra = pt ? rA[g ^ 7]    : rA[g];
            float2 ct2 = pt ? cT[g ^ 7]  : cT[g];
            ull rp = mul2(bcast2(realH * rt), ra);
            float2 d = cmulc(cH, ct2);
            vr[k] = mul2(rp, bcast2(d.x));
            vi[k] = mul2(rp, bcast2(d.y));
        }
    }

    // ---- layer 1: D_alpha1 -> 12 gates (4 passes) -> D_beta1
    diag_p0(sEA[1], T, vr, vi);
    apply3(sC[1], sS[1], 0, vr, vi);
    stp(sre, sim, 0, T, vr, vi);
    __syncthreads();
    ldp(sre, sim, 1, T, vr, vi);
    apply3(sC[1], sS[1], 3, vr, vi);
    stp(sre, sim, 1, T, vr, vi);
    __syncthreads();
    ldp(sre, sim, 2, T, vr, vi);
    apply3(sC[1], sS[1], 6, vr, vi);
    stp(sre, sim, 2, T, vr, vi);
    __syncthreads();
    ldp(sre, sim, 3, T, vr, vi);
    apply3(sC[1], sS[1], 9, vr, vi);
    diag_p3(sEB[1], T, vr, vi);
    stp(sre, sim, 3, T, vr, vi);
    __syncthreads();

    // ---- layer 0: P gather -> D_alpha0 -> 12 gates -> D_beta0 -> g_v2
    ldp0_gray(sre, sim, T, vr, vi);
    // CRITICAL: the gray gather reads slots owned by OTHER threads (permuted).
    // All reads must complete before any thread overwrites its own slots below.
    __syncthreads();
    diag_p0(sEA[0], T, vr, vi);
    apply3(sC[0], sS[0], 0, vr, vi);
    stp(sre, sim, 0, T, vr, vi);
    __syncthreads();
    ldp(sre, sim, 1, T, vr, vi);
    apply3(sC[0], sS[0], 3, vr, vi);
    stp(sre, sim, 1, T, vr, vi);
    __syncthreads();
    ldp(sre, sim, 2, T, vr, vi);
    apply3(sC[0], sS[0], 6, vr, vi);
    stp(sre, sim, 2, T, vr, vi);
    __syncthreads();
    ldp(sre, sim, 3, T, vr, vi);
    apply3(sC[0], sS[0], 9, vr, vi);
    diag_p3(sEB[0], T, vr, vi);
#pragma unroll
    for (int k = 0; k < 8; ++k) {
        int n = idx_p(3, T, k);
        g_v2[n] = make_ulonglong2(vr[k], vi[k]);
    }
}

// ====================== CONTRACT =============================================
// blockIdx: quarter = bx & 3 (hi rows [q*16, q*16+16)), gp = bx >> 2 owns
// 64 batch elements processed in TWO sequential 32-lane phases (keeps register
// pressure at the proven single-group level while amortizing the v load 2x).
__global__ __launch_bounds__(CT, 2)
void contract_kernel(const float* __restrict__ x, int B)
{
    __shared__ ulonglong2 sv[1024];          // quarter v slice: [row16][lo64]
    __shared__ ull pre[2][8][32], pim[2][8][32];

    const int tid = threadIdx.x;
    const int lane = tid & 31;
    const int warpid = tid >> 5;
    const int quarter = blockIdx.x & 3;
    const int gp = blockIdx.x >> 2;

#pragma unroll
    for (int i = 0; i < 4; ++i)
        sv[tid + i * CT] = g_v2[quarter * 1024 + tid + i * CT];
    __syncthreads();

    const ulonglong2* vw = sv + warpid * 128;

#pragma unroll 1
    for (int ph = 0; ph < 2; ++ph) {
        int b = gp * 64 + ph * 32 + lane;
        int bb = (b < B) ? b : (B - 1);

        ull  b2p[8];
        float a2f[8], hfac[2];
        {
            float fc[NQ], fs[NQ];
#pragma unroll
            for (int w = 0; w < NQ; ++w) {
                float s, c; __sincosf(0.5f * x[bb * NQ + w], &s, &c);
                fc[w] = c; fs[w] = s;
            }
#pragma unroll
            for (int i = 0; i < 8; ++i) {
                a2f[i] = ((i & 1) ? fs[8] : fc[8]) *
                         ((i & 2) ? fs[7] : fc[7]) *
                         ((i & 4) ? fs[6] : fc[6]);
                b2p[i] = bcast2(((i & 1) ? fs[11] : fc[11]) *
                                ((i & 2) ? fs[10] : fc[10]) *
                                ((i & 4) ? fs[9]  : fc[9]));
            }
#pragma unroll
            for (int t = 0; t < 2; ++t) {
                int row = quarter * 16 + warpid * 2 + t;  // hi bits 5..0 -> wires 0..5
                hfac[t] = (((row >> 5) & 1) ? fs[0] : fc[0]) *
                          (((row >> 4) & 1) ? fs[1] : fc[1]) *
                          (((row >> 3) & 1) ? fs[2] : fc[2]) *
                          (((row >> 2) & 1) ? fs[3] : fc[3]) *
                          (((row >> 1) & 1) ? fs[4] : fc[4]) *
                          (((row >> 0) & 1) ? fs[5] : fc[5]);
            }
        }

        ull ir[2] = {0ULL, 0ULL}, ii[2] = {0ULL, 0ULL};
#pragma unroll
        for (int i = 0; i < 8; ++i) {
            ull tr[2] = {0ULL, 0ULL}, ti[2] = {0ULL, 0ULL};
#pragma unroll
            for (int j = 0; j < 8; ++j) {
#pragma unroll
                for (int t = 0; t < 2; ++t) {
                    ulonglong2 v = vw[t * 64 + i * 8 + j];   // warp-broadcast LDS
                    tr[t] = fma2(v.x, b2p[j], tr[t]);
                    ti[t] = fma2(v.y, b2p[j], ti[t]);
                }
            }
            ull ai = bcast2(a2f[i]);
#pragma unroll
            for (int t = 0; t < 2; ++t) {
                ir[t] = fma2(ai, tr[t], ir[t]);
                ii[t] = fma2(ai, ti[t], ii[t]);
            }
        }

        ull amp_re = 0ULL, amp_im = 0ULL;
#pragma unroll
        for (int t = 0; t < 2; ++t) {
            amp_re = fma2(bcast2(hfac[t]), ir[t], amp_re);
            amp_im = fma2(bcast2(hfac[t]), ii[t], amp_im);
        }
        pre[ph][warpid][lane] = amp_re;
        pim[ph][warpid][lane] = amp_im;
    }
    __syncthreads();

    // Warp 0 reduces phase-0 group, warp 1 reduces phase-1 group (fixed order).
    if (warpid < 2) {
        ull re = pre[warpid][0][lane], im = pim[warpid][0][lane];
#pragma unroll
        for (int w = 1; w < 8; ++w) {
            re = add2(re, pre[warpid][w][lane]);
            im = add2(im, pim[warpid][w][lane]);
        }
        g_part4[quarter][gp * 2 + warpid][lane] = make_ulonglong2(re, im);
    }
}

// ====================== COMBINE ==============================================
__global__ __launch_bounds__(CT)
void combine_kernel(float* __restrict__ out, int B)
{
    int b = blockIdx.x * CT + threadIdx.x;
    if (b >= B) return;
    int group = b >> 5, lane = b & 31;
    ull re = 0ULL, im = 0ULL;
#pragma unroll
    for (int q = 0; q < 4; ++q) {
        ulonglong2 p = g_part4[q][group][lane];
        re = add2(re, p.x);
        im = add2(im, p.y);
    }
    float r0, r1, i0, i1;
    unpack2(re, r0, r1);
    unpack2(im, i0, i1);
    float q0 = r0 * r0 + i0 * i0;
    float q1 = r1 * r1 + i1 * i1;
    float inv = 1.0f / (q0 + q1);
    ((float2*)out)[b] = make_float2(q0 * inv, q1 * inv);
}

extern "C" void kernel_launch(void* const* d_in, const int* in_sizes, int n_in,
                              void* d_out, int out_size) {
    const float* x      = (const float*)d_in[0];  // (B, 12) float32
    const float* params = (const float*)d_in[1];  // (3, 12, 3) float32
    float* out = (float*)d_out;                   // (B, 2) float32
    int B = in_sizes[0] / NQ;
    int gp64 = (B + 63) / 64;

    // Unconditional every call (no static guards): host-side, capture-legal.
    cudaFuncSetAttribute(setup_kernel,
                         cudaFuncAttributeMaxDynamicSharedMemorySize, 66560);

    setup_kernel<<<1, ST, 66560>>>(params);
    contract_kernel<<<gp64 * 4, CT>>>(x, B);
    combine_kernel<<<(B + CT - 1) / CT, CT>>>(out, B);
}

// round 11
// speedup vs baseline: 4.2410x; 4.2410x over previous
#include <cuda_runtime.h>

#define NQ 12
#define DIM 4096
#define ST 512     // setup threads
#define CT 256     // contract threads

typedef unsigned long long ull;

// Row vectors v_j[n] = <j|U|n>, packed lanes (j=0, j=1): (re, im) per n.
__device__ ulonglong2 g_v2[DIM];
// Split-K partials: [half][group32][lane] -> (re, im) packed.
__device__ ulonglong2 g_part2[2][256][32];

// ---- packed f32x2 helpers ----
__device__ __forceinline__ ull pack2(float lo, float hi) {
    ull r; asm("mov.b64 %0, {%1, %2};" : "=l"(r) : "f"(lo), "f"(hi)); return r;
}
__device__ __forceinline__ ull bcast2(float v) { return pack2(v, v); }
__device__ __forceinline__ void unpack2(ull v, float& lo, float& hi) {
    asm("mov.b64 {%0, %1}, %2;" : "=f"(lo), "=f"(hi) : "l"(v));
}
__device__ __forceinline__ ull fma2(ull a, ull b, ull c) {
    ull d; asm("fma.rn.f32x2 %0, %1, %2, %3;" : "=l"(d) : "l"(a), "l"(b), "l"(c)); return d;
}
__device__ __forceinline__ ull mul2(ull a, ull b) {
    ull d; asm("mul.rn.f32x2 %0, %1, %2;" : "=l"(d) : "l"(a), "l"(b)); return d;
}
__device__ __forceinline__ ull add2(ull a, ull b) {
    ull d; asm("add.rn.f32x2 %0, %1, %2;" : "=l"(d) : "l"(a), "l"(b)); return d;
}

// Shared-memory mapping with 65-row pitch: bank-conflict-free for all passes.
__device__ __forceinline__ int pnm(int n) { return 65 * (n >> 6) + (n & 63); }

// 12-bit inverse Gray code (prefix XOR).
__device__ __forceinline__ int grayinv(int i) {
    i ^= i >> 1; i ^= i >> 2; i ^= i >> 4; i ^= i >> 8;
    return i;
}

__device__ __forceinline__ float2 cmulc(float2 a, float2 b) {
    return make_float2(a.x * b.x - a.y * b.y, a.x * b.y + a.y * b.x);
}
__device__ __forceinline__ float2 selE(float2 e, int bit) {   // bit ? e : conj(e)
    return make_float2(e.x, bit ? e.y : -e.y);
}
__device__ __forceinline__ void crot(ull& r, ull& i, float2 f) {
    ull fx = bcast2(f.x), fy = bcast2(f.y), nfy = bcast2(-f.y);
    ull nr = fma2(fx, r, mul2(nfy, i));
    ull ni = fma2(fx, i, mul2(fy, r));
    r = nr; i = ni;
}

// Per-pass index assignment (T = tid 0..511, k = 0..7 owns the pass's 3 bits).
__device__ __forceinline__ int idx_p(int p, int T, int k) {
    int t6 = T & 63, th = T >> 6;
    if (p == 0) return (t6 << 6) | (th << 3) | k;     // k = bits 0-2
    if (p == 1) return (t6 << 6) | (k << 3) | th;     // k = bits 3-5
    if (p == 2) return (th << 9) | (k << 6) | t6;     // k = bits 6-8
    return (k << 9) | (th << 6) | t6;                 // k = bits 9-11
}

// Row x RY gates: 3 gates, gate m on k-bit m (wire = 11 - basebit - m).
__device__ __forceinline__ void apply3(const float* C, const float* S,
                                       int basebit, ull* vr, ull* vi)
{
#pragma unroll
    for (int m = 0; m < 3; ++m) {
        int wire = 11 - basebit - m;
        float c = C[wire], s = S[wire];
        ull c2 = bcast2(c), s2 = bcast2(s), ns2 = bcast2(-s);
#pragma unroll
        for (int k = 0; k < 8; ++k) {
            if (k & (1 << m)) continue;
            int k1 = k | (1 << m);
            ull ar = vr[k], ai = vi[k], br = vr[k1], bi = vi[k1];
            vr[k]  = fma2(c2, ar, mul2(s2, br));
            vi[k]  = fma2(c2, ai, mul2(s2, bi));
            vr[k1] = fma2(c2, br, mul2(ns2, ar));
            vi[k1] = fma2(c2, bi, mul2(ns2, ai));
        }
    }
}

__device__ __forceinline__ void ldp(const ull* sre, const ull* sim, int p, int T,
                                    ull* vr, ull* vi) {
#pragma unroll
    for (int k = 0; k < 8; ++k) {
        int pn = pnm(idx_p(p, T, k));
        vr[k] = sre[pn]; vi[k] = sim[pn];
    }
}
__device__ __forceinline__ void ldp0_gray(const ull* sre, const ull* sim, int T,
                                          ull* vr, ull* vi) {
#pragma unroll
    for (int k = 0; k < 8; ++k) {
        int pn = pnm(grayinv(idx_p(0, T, k)));
        vr[k] = sre[pn]; vi[k] = sim[pn];
    }
}
__device__ __forceinline__ void stp(ull* sre, ull* sim, int p, int T,
                                    const ull* vr, const ull* vi) {
#pragma unroll
    for (int k = 0; k < 8; ++k) {
        int pn = pnm(idx_p(p, T, k));
        sre[pn] = vr[k]; sim[pn] = vi[k];
    }
}

// Diagonal (pass-0 layout). idx bits [11..6]=T&63, [5..3]=T>>6, [2..0]=k.
__device__ __forceinline__ void diag_p0(const float2* E, int T, ull* vr, ull* vi) {
    float2 tp = selE(E[0], (T >> 5) & 1);
#pragma unroll
    for (int w = 1; w < 6; ++w) tp = cmulc(tp, selE(E[w], (T >> (5 - w)) & 1));
#pragma unroll
    for (int w = 6; w < 9; ++w) tp = cmulc(tp, selE(E[w], (T >> (14 - w)) & 1));
#pragma unroll
    for (int k = 0; k < 8; ++k) {
        float2 kt = cmulc(selE(E[9], (k >> 2) & 1),
                          cmulc(selE(E[10], (k >> 1) & 1), selE(E[11], k & 1)));
        crot(vr[k], vi[k], cmulc(tp, kt));
    }
}

// Diagonal (pass-3 layout). idx bits [11..9]=k, [8..0]=T.
__device__ __forceinline__ void diag_p3(const float2* E, int T, ull* vr, ull* vi) {
    float2 tp = selE(E[3], (T >> 8) & 1);
#pragma unroll
    for (int w = 4; w < 12; ++w) tp = cmulc(tp, selE(E[w], (T >> (11 - w)) & 1));
#pragma unroll
    for (int k = 0; k < 8; ++k) {
        float2 kt = cmulc(selE(E[0], (k >> 2) & 1),
                          cmulc(selE(E[1], (k >> 1) & 1), selE(E[2], k & 1)));
        crot(vr[k], vi[k], cmulc(tp, kt));
    }
}

// ====================== SETUP: v = rows <j|U (512 threads, radix-8) =========
__global__ __launch_bounds__(ST)
void setup_kernel(const float* __restrict__ params)
{
    extern __shared__ ull smem[];
    ull* sre = smem;           // 64 rows x 65 pitch = 4160 ull
    ull* sim = smem + 4160;
    __shared__ float  sC[3][12], sS[3][12];
    __shared__ float2 sEA[3][12], sEB[3][12];   // e^{+i alpha/2}, e^{+i beta/2}

    const int T = threadIdx.x;

    if (T < 36) {
        int layer = T / 12, q = T % 12;
        const float* p = params + T * 3;
        float sa, ca; sincosf(0.5f * p[0], &sa, &ca);
        float sb, cb; sincosf(0.5f * p[1], &sb, &cb);
        float sc, cc; sincosf(0.5f * p[2], &sc, &cc);
        float2 m00 = make_float2( cb * ca, -sb * sa);
        float2 m10 = make_float2( cb * sa, -sb * ca);
        float2 e0 = make_float2(cc, -sc);
        float2 e1 = make_float2(cc,  sc);
        float2 u00 = cmulc(e0, m00);
        float2 u10 = cmulc(e1, m10);
        float ct = sqrtf(u00.x * u00.x + u00.y * u00.y);
        float st = sqrtf(u10.x * u10.x + u10.y * u10.y);
        float ApB = -2.0f * atan2f(u00.y, u00.x);
        float AmB =  2.0f * atan2f(u10.y, u10.x);
        float alpha = 0.5f * (ApB + AmB);
        float beta  = 0.5f * (ApB - AmB);
        sC[layer][q] = ct; sS[layer][q] = st;
        float s2, c2;
        sincosf(0.5f * alpha, &s2, &c2); sEA[layer][q] = make_float2(c2, s2);
        sincosf(0.5f * beta,  &s2, &c2); sEB[layer][q] = make_float2(c2, s2);
    }
    __syncthreads();

    ull vr[8], vi[8];

    // ---- Analytic layer-2 row at m = grayinv(idx), pass-0 ownership.
    {
        int t6 = T & 63, th = T >> 6;
        int thi = (t6 << 3) | th;               // idx bits 11..3
        int pt = __popc(thi) & 1;
        int mh = thi ^ (thi >> 1); mh ^= mh >> 2; mh ^= mh >> 4; mh ^= mh >> 8;
        float realH = 1.0f;
        float2 cH = make_float2(1.0f, 0.0f);
#pragma unroll
        for (int w = 0; w < 9; ++w) {           // wires 0..8 <- mh bits 8..0
            int bit = (mh >> (8 - w)) & 1;
            realH *= bit ? -sS[2][w] : sC[2][w];
            cH = cmulc(cH, selE(sEB[2][w], bit));
        }
        float realT[8]; ull rA[8]; float2 cT[8];
#pragma unroll
        for (int m = 0; m < 8; ++m) {
            int b2 = (m >> 2) & 1, b1 = (m >> 1) & 1, b0 = m & 1;
            realT[m] = (b2 ? -sS[2][9] : sC[2][9]) * (b1 ? -sS[2][10] : sC[2][10]);
            rA[m] = pack2(b0 ? -sS[2][11] : sC[2][11],
                          b0 ?  sC[2][11] : sS[2][11]);
            cT[m] = cmulc(selE(sEB[2][9], b2),
                          cmulc(selE(sEB[2][10], b1), selE(sEB[2][11], b0)));
        }
#pragma unroll
        for (int k = 0; k < 8; ++k) {
            int g = (k ^ (k >> 1) ^ (k >> 2)) & 7;
            float rt = pt ? realT[g ^ 7] : realT[g];
            ull   ra = pt ? rA[g ^ 7]    : rA[g];
            float2 ct2 = pt ? cT[g ^ 7]  : cT[g];
            ull rp = mul2(bcast2(realH * rt), ra);
            float2 d = cmulc(cH, ct2);
            vr[k] = mul2(rp, bcast2(d.x));
            vi[k] = mul2(rp, bcast2(d.y));
        }
    }

    // ---- layer 1: D_alpha1 -> 12 gates (4 passes) -> D_beta1
    diag_p0(sEA[1], T, vr, vi);
    apply3(sC[1], sS[1], 0, vr, vi);
    stp(sre, sim, 0, T, vr, vi);
    __syncthreads();
    ldp(sre, sim, 1, T, vr, vi);
    apply3(sC[1], sS[1], 3, vr, vi);
    stp(sre, sim, 1, T, vr, vi);
    __syncthreads();
    ldp(sre, sim, 2, T, vr, vi);
    apply3(sC[1], sS[1], 6, vr, vi);
    stp(sre, sim, 2, T, vr, vi);
    __syncthreads();
    ldp(sre, sim, 3, T, vr, vi);
    apply3(sC[1], sS[1], 9, vr, vi);
    diag_p3(sEB[1], T, vr, vi);
    stp(sre, sim, 3, T, vr, vi);
    __syncthreads();

    // ---- layer 0: P gather -> D_alpha0 -> 12 gates -> D_beta0 -> g_v2
    ldp0_gray(sre, sim, T, vr, vi);
    // CRITICAL: the gray gather reads slots owned by OTHER threads (permuted).
    // All reads must complete before any thread overwrites its own slots below.
    __syncthreads();
    diag_p0(sEA[0], T, vr, vi);
    apply3(sC[0], sS[0], 0, vr, vi);
    stp(sre, sim, 0, T, vr, vi);
    __syncthreads();
    ldp(sre, sim, 1, T, vr, vi);
    apply3(sC[0], sS[0], 3, vr, vi);
    stp(sre, sim, 1, T, vr, vi);
    __syncthreads();
    ldp(sre, sim, 2, T, vr, vi);
    apply3(sC[0], sS[0], 6, vr, vi);
    stp(sre, sim, 2, T, vr, vi);
    __syncthreads();
    ldp(sre, sim, 3, T, vr, vi);
    apply3(sC[0], sS[0], 9, vr, vi);
    diag_p3(sEB[0], T, vr, vi);
#pragma unroll
    for (int k = 0; k < 8; ++k) {
        int n = idx_p(3, T, k);
        g_v2[n] = make_ulonglong2(vr[k], vi[k]);
    }
}

// ====================== CONTRACT (half split, R6-proven core) ===============
// blockIdx: half = bx & 1 (hi rows [half*32, half*32+32)), group = bx >> 1.
// Warp w handles 4 local rows [w*4, w*4+4); lanes = 32 batch elements.
__global__ __launch_bounds__(CT)
void contract_kernel(const float* __restrict__ x, int B)
{
    __shared__ ulonglong2 sv[2048];          // this half's v slice: [row32][lo64]
    __shared__ ull pre[8][32], pim[8][32];

    const int tid = threadIdx.x;
    const int lane = tid & 31;
    const int warpid = tid >> 5;
    const int half = blockIdx.x & 1;
    const int group = blockIdx.x >> 1;

#pragma unroll
    for (int i = 0; i < 8; ++i)
        sv[tid + i * CT] = g_v2[half * 2048 + tid + i * CT];

    int b = group * 32 + lane;
    int bb = (b < B) ? b : (B - 1);

    ull  b2p[8];
    float a2f[8], hfac[4];
    {
        float fc[NQ], fs[NQ];
#pragma unroll
        for (int w = 0; w < NQ; ++w) {
            float s, c; __sincosf(0.5f * x[bb * NQ + w], &s, &c);
            fc[w] = c; fs[w] = s;
        }
#pragma unroll
        for (int i = 0; i < 8; ++i) {
            a2f[i] = ((i & 1) ? fs[8] : fc[8]) *
                     ((i & 2) ? fs[7] : fc[7]) *
                     ((i & 4) ? fs[6] : fc[6]);
            b2p[i] = bcast2(((i & 1) ? fs[11] : fc[11]) *
                            ((i & 2) ? fs[10] : fc[10]) *
                            ((i & 4) ? fs[9]  : fc[9]));
        }
#pragma unroll
        for (int t = 0; t < 4; ++t) {
            int row = half * 32 + warpid * 4 + t;   // hi bits 5..0 -> wires 0..5
            hfac[t] = (((row >> 5) & 1) ? fs[0] : fc[0]) *
                      (((row >> 4) & 1) ? fs[1] : fc[1]) *
                      (((row >> 3) & 1) ? fs[2] : fc[2]) *
                      (((row >> 2) & 1) ? fs[3] : fc[3]) *
                      (((row >> 1) & 1) ? fs[4] : fc[4]) *
                      (((row >> 0) & 1) ? fs[5] : fc[5]);
        }
    }
    __syncthreads();

    const ulonglong2* vw = sv + warpid * 4 * 64;
    ull ir[4] = {0ULL, 0ULL, 0ULL, 0ULL}, ii[4] = {0ULL, 0ULL, 0ULL, 0ULL};

#pragma unroll
    for (int i = 0; i < 8; ++i) {
        ull tr[4] = {0ULL, 0ULL, 0ULL, 0ULL}, ti[4] = {0ULL, 0ULL, 0ULL, 0ULL};
#pragma unroll
        for (int j = 0; j < 8; ++j) {
#pragma unroll
            for (int t = 0; t < 4; ++t) {
                ulonglong2 v = vw[t * 64 + i * 8 + j];   // warp-broadcast LDS
                tr[t] = fma2(v.x, b2p[j], tr[t]);
                ti[t] = fma2(v.y, b2p[j], ti[t]);
            }
        }
        ull ai = bcast2(a2f[i]);
#pragma unroll
        for (int t = 0; t < 4; ++t) {
            ir[t] = fma2(ai, tr[t], ir[t]);
            ii[t] = fma2(ai, ti[t], ii[t]);
        }
    }

    ull amp_re = 0ULL, amp_im = 0ULL;
#pragma unroll
    for (int t = 0; t < 4; ++t) {
        amp_re = fma2(bcast2(hfac[t]), ir[t], amp_re);
        amp_im = fma2(bcast2(hfac[t]), ii[t], amp_im);
    }
    pre[warpid][lane] = amp_re;
    pim[warpid][lane] = amp_im;
    __syncthreads();

    if (warpid == 0) {
        ull re = pre[0][lane], im = pim[0][lane];
#pragma unroll
        for (int w = 1; w < 8; ++w) {
            re = add2(re, pre[w][lane]);
            im = add2(im, pim[w][lane]);
        }
        g_part2[half][group][lane] = make_ulonglong2(re, im);
    }
}

// ====================== COMBINE ==============================================
__global__ __launch_bounds__(CT)
void combine_kernel(float* __restrict__ out, int B)
{
    int b = blockIdx.x * CT + threadIdx.x;
    if (b >= B) return;
    int group = b >> 5, lane = b & 31;
    ulonglong2 p0 = g_part2[0][group][lane];
    ulonglong2 p1 = g_part2[1][group][lane];
    ull re = add2(p0.x, p1.x);
    ull im = add2(p0.y, p1.y);
    float r0, r1, i0, i1;
    unpack2(re, r0, r1);
    unpack2(im, i0, i1);
    float q0 = r0 * r0 + i0 * i0;
    float q1 = r1 * r1 + i1 * i1;
    float inv = 1.0f / (q0 + q1);
    ((float2*)out)[b] = make_float2(q0 * inv, q1 * inv);
}

extern "C" void kernel_launch(void* const* d_in, const int* in_sizes, int n_in,
                              void* d_out, int out_size) {
    const float* x      = (const float*)d_in[0];  // (B, 12) float32
    const float* params = (const float*)d_in[1];  // (3, 12, 3) float32
    float* out = (float*)d_out;                   // (B, 2) float32
    int B = in_sizes[0] / NQ;
    int groups = (B + 31) / 32;

    // Unconditional every call (no static guards): host-side, capture-legal.
    cudaFuncSetAttribute(setup_kernel,
                         cudaFuncAttributeMaxDynamicSharedMemorySize, 66560);

    setup_kernel<<<1, ST, 66560>>>(params);
    contract_kernel<<<groups * 2, CT>>>(x, B);
    combine_kernel<<<(B + CT - 1) / CT, CT>>>(out, B);
}

// round 12
// speedup vs baseline: 13.6573x; 3.2203x over previous
#include <cuda_runtime.h>

#define NQ 12
#define BT 128   // threads per block, 1 batch element per thread

__device__ __forceinline__ float2 cmulc(float2 a, float2 b) {
    return make_float2(a.x * b.x - a.y * b.y, a.x * b.y + a.y * b.x);
}
__device__ __forceinline__ float2 caddc(float2 a, float2 b) {
    return make_float2(a.x + b.x, a.y + b.y);
}

// One kernel does everything.
//
// Math: amp_j(b) = sum_{a,b,n} G2[g(j),a] G1[g(a),b] G0[g(b),n] psi0[n],
// g(n) = n ^ (n>>1) (validated CNOT-chain permutation; bit-local:
// g(a)_p = a_p ^ a_{p+1}, a_12 = 0). All G factor per bit (wire w <-> bit 11-w)
// and psi0 is a product state, so amp is a transfer-matrix chain over bits
// p = 11..0 with bond sigma_p = (a_p, b_p) in {0..3}:
//   T_p[s][s'] = U2_p[c_p, a] * U1_p[a^a', b] * (U0_p[b^b',0] cos_p + U0_p[b^b',1] sin_p)
// with c_p = 0 for p>=1 and c_0 = j (g(j)=j for j in {0,1}); cos_p/sin_p from
// x[11-p]. Batch-independent parts: K{0,1}_p (4x4 complex), built per CTA.
__global__ __launch_bounds__(BT)
void qnn_mps_kernel(const float* __restrict__ x,
                    const float* __restrict__ params,
                    float* __restrict__ out, int B)
{
    __shared__ float2 sU[3][12][4];        // fused gates  [layer][wire][r*2+s]
    __shared__ float2 sK[11][2][4][4];     // [p-1][n-bit s][sigma][sigma']
    __shared__ float2 sKap[2][2][4];       // p=0 row-summed: [j][s][sigma']

    const int tid = threadIdx.x;

    // ---- fused gate U = RZ(c) RX(b) RY(a) per (layer, wire) [validated] ----
    if (tid < 36) {
        const float* p = params + tid * 3;
        float sa, ca; sincosf(0.5f * p[0], &sa, &ca);
        float sb, cb; sincosf(0.5f * p[1], &sb, &cb);
        float sc, cc; sincosf(0.5f * p[2], &sc, &cc);
        float2 m00 = make_float2( cb * ca, -sb * sa);
        float2 m01 = make_float2(-cb * sa, -sb * ca);
        float2 m10 = make_float2( cb * sa, -sb * ca);
        float2 m11 = make_float2( cb * ca,  sb * sa);
        float2 e0 = make_float2(cc, -sc);
        float2 e1 = make_float2(cc,  sc);
        int layer = tid / 12, wire = tid % 12;
        sU[layer][wire][0] = cmulc(e0, m00);   // U[0][0]
        sU[layer][wire][1] = cmulc(e0, m01);   // U[0][1]
        sU[layer][wire][2] = cmulc(e1, m10);   // U[1][0]
        sU[layer][wire][3] = cmulc(e1, m11);   // U[1][1]
    }
    __syncthreads();

    // ---- K tensors: 352 bulk entries (p=1..11) + 16 boundary entries (p=0) --
    for (int e = tid; e < 368; e += BT) {
        if (e < 352) {
            int p   = e / 32 + 1;          // 1..11
            int w   = 11 - p;              // wire for bit p
            int rem = e % 32;
            int s   = rem >> 4;            // n-bit of this position
            int sg  = (rem >> 2) & 3;      // sigma  = a + 2b
            int sgp = rem & 3;             // sigma' = a' + 2b'
            int a = sg & 1,  bq = sg >> 1;
            int ap = sgp & 1, bp = sgp >> 1;
            sK[p - 1][s][sg][sgp] =
                cmulc(cmulc(sU[2][w][a],                   // U2[0][a]
                            sU[1][w][((a ^ ap) << 1) | bq]),  // U1[a^a'][b]
                      sU[0][w][((bq ^ bp) << 1) | s]);        // U0[b^b'][s]
        } else {
            int r   = e - 352;
            int j   = r >> 3;
            int s   = (r >> 2) & 1;
            int sgp = r & 3;
            int ap = sgp & 1, bp = sgp >> 1;
            float2 acc = make_float2(0.0f, 0.0f);
#pragma unroll
            for (int sg = 0; sg < 4; ++sg) {      // sum over sigma_0 (free)
                int a = sg & 1, bq = sg >> 1;
                acc = caddc(acc,
                    cmulc(cmulc(sU[2][11][(j << 1) | a],          // U2[j][a]
                                sU[1][11][((a ^ ap) << 1) | bq]),
                          sU[0][11][((bq ^ bp) << 1) | s]));
            }
            sKap[j][s][sgp] = acc;
        }
    }
    __syncthreads();

    // ---- per-batch transfer-matrix chain -----------------------------------
    const int b  = blockIdx.x * BT + tid;
    const int bb = (b < B) ? b : (B - 1);

    float fc[NQ], fs[NQ];
#pragma unroll
    for (int w = 0; w < NQ; ++w) {
        float s, c; __sincosf(0.5f * x[bb * NQ + w], &s, &c);
        fc[w] = c; fs[w] = s;
    }

    // p = 11 (wire 0): sigma_12 = 0 boundary -> column 0 of K_11
    float2 wv[4];
#pragma unroll
    for (int sg = 0; sg < 4; ++sg) {
        float2 k0 = sK[10][0][sg][0], k1 = sK[10][1][sg][0];
        wv[sg] = make_float2(fc[0] * k0.x + fs[0] * k1.x,
                             fc[0] * k0.y + fs[0] * k1.y);
    }

    // p = 10..1 (wire 11-p): w <- (c*K0 + s*K1) w
#pragma unroll
    for (int p = 10; p >= 1; --p) {
        float c = fc[11 - p], s = fs[11 - p];
        float2 nw[4];
#pragma unroll
        for (int sg = 0; sg < 4; ++sg) {
            float2 a0 = make_float2(0.0f, 0.0f);
            float2 a1 = make_float2(0.0f, 0.0f);
#pragma unroll
            for (int sp = 0; sp < 4; ++sp) {
                a0 = caddc(a0, cmulc(sK[p - 1][0][sg][sp], wv[sp]));
                a1 = caddc(a1, cmulc(sK[p - 1][1][sg][sp], wv[sp]));
            }
            nw[sg] = make_float2(c * a0.x + s * a1.x,
                                 c * a0.y + s * a1.y);
        }
#pragma unroll
        for (int sg = 0; sg < 4; ++sg) wv[sg] = nw[sg];
    }

    // p = 0 (wire 11): boundary row-sums, two j variants
    float pr[2];
#pragma unroll
    for (int j = 0; j < 2; ++j) {
        float2 a0 = make_float2(0.0f, 0.0f);
        float2 a1 = make_float2(0.0f, 0.0f);
#pragma unroll
        for (int sp = 0; sp < 4; ++sp) {
            a0 = caddc(a0, cmulc(sKap[j][0][sp], wv[sp]));
            a1 = caddc(a1, cmulc(sKap[j][1][sp], wv[sp]));
        }
        float re = fc[11] * a0.x + fs[11] * a1.x;
        float im = fc[11] * a0.y + fs[11] * a1.y;
        pr[j] = re * re + im * im;
    }

    if (b < B) {
        float inv = 1.0f / (pr[0] + pr[1]);
        ((float2*)out)[b] = make_float2(pr[0] * inv, pr[1] * inv);
    }
}

extern "C" void kernel_launch(void* const* d_in, const int* in_sizes, int n_in,
                              void* d_out, int out_size) {
    const float* x      = (const float*)d_in[0];  // (B, 12) float32
    const float* params = (const float*)d_in[1];  // (3, 12, 3) float32
    float* out = (float*)d_out;                   // (B, 2) float32
    int B = in_sizes[0] / NQ;

    qnn_mps_kernel<<<(B + BT - 1) / BT, BT>>>(x, params, out, B);
}